// round 15
// baseline (speedup 1.0000x reference)
#include <cuda_runtime.h>
#include <cuda_fp16.h>
#include <cstdint>

#define BB 2
#define CC 512
#define NN 4096
#define GG 32
#define CGG 16
#define SM_SCALE 0.044194173824159216f

// ---------------- scratch (__device__ globals; allocation-free rule) --------
__device__ __half g_hn   [(size_t)BB * NN * CC];       // groupnorm out [b*n, c]
__device__ __half g_qk   [(size_t)BB * NN * 2 * CC];   // [b*n, 1024]: q 0-511, k 512-1023
__device__ __half g_vt   [(size_t)CC * BB * NN];       // [c, b*n]
__device__ __half g_attnT[(size_t)BB * NN * NN];       // exp(logits)*2^-12, [b, j, i]
__device__ __half g_h2   [(size_t)BB * NN * CC];       // [b, j, c]
__device__ __half g_w16  [4][(size_t)CC * CC];         // wq, wk, wv, wp fp16 (wq|wk contiguous)
__device__ float  g_sum  [BB * NN];                    // colsum of exp
__device__ float  g_bqk  [2 * CC];                     // [bq ; bk]
__device__ float  g_gnsc [BB * CC];                    // per-channel scale
__device__ float  g_gnsh [BB * CC];                    // per-channel shift

// ---------------------------------------------------------------------------
__device__ __forceinline__ uint32_t smem_u32(const void* p) {
    uint32_t a;
    asm("{ .reg .u64 t; cvta.to.shared.u64 t, %1; cvt.u32.u64 %0, t; }"
        : "=r"(a) : "l"(p));
    return a;
}
__device__ __forceinline__ void cp_async16(uint32_t saddr, const void* g) {
    asm volatile("cp.async.cg.shared.global [%0], [%1], 16;" :: "r"(saddr), "l"(g));
}
__device__ __forceinline__ void ldsm_x4(uint32_t d[4], uint32_t addr) {
    asm volatile("ldmatrix.sync.aligned.m8n8.x4.shared.b16 {%0,%1,%2,%3}, [%4];"
                 : "=r"(d[0]), "=r"(d[1]), "=r"(d[2]), "=r"(d[3]) : "r"(addr));
}
__device__ __forceinline__ void mma_f16(float d[4], const uint32_t a[4],
                                        uint32_t b0, uint32_t b1) {
    asm volatile(
        "mma.sync.aligned.m16n8k16.row.col.f32.f16.f16.f32 "
        "{%0,%1,%2,%3}, {%4,%5,%6,%7}, {%8,%9}, {%0,%1,%2,%3};"
        : "+f"(d[0]), "+f"(d[1]), "+f"(d[2]), "+f"(d[3])
        : "r"(a[0]), "r"(a[1]), "r"(a[2]), "r"(a[3]), "r"(b0), "r"(b1));
}

// exp(SM_SCALE*v) * 2^-12 on the FMA pipe (no MUFU).
__device__ __forceinline__ float fast_exp_scaled(float v) {
    float t = v * (SM_SCALE * 1.4426950408889634f);
    float z = t + 12582912.f;                 // 1.5*2^23: round-to-nearest
    int   i = __float_as_int(z) - 0x4B400000;
    float f = t - (z - 12582912.f);           // frac in [-0.5, 0.5]
    float p =            1.3333649e-3f;
    p = fmaf(p, f, 9.6179357e-3f);
    p = fmaf(p, f, 5.5504109e-2f);
    p = fmaf(p, f, 2.4022604e-1f);
    p = fmaf(p, f, 6.9314718e-1f);
    p = fmaf(p, f, 1.0f);
    return p * __int_as_float((i + 127 - 12) << 23);   // fold 2^-12
}

// ---------------------------------------------------------------------------
// Weights fp32 -> fp16 (all four in one launch; y selects the matrix)
// ---------------------------------------------------------------------------
__global__ void f2h4_kernel(const float* __restrict__ s0, const float* __restrict__ s1,
                            const float* __restrict__ s2, const float* __restrict__ s3,
                            __half* __restrict__ dst) {
    const float* s = (blockIdx.y == 0) ? s0 : (blockIdx.y == 1) ? s1
                   : (blockIdx.y == 2) ? s2 : s3;
    const size_t off = (size_t)blockIdx.y * CC * CC;
    const int i = (blockIdx.x * 256 + threadIdx.x) * 4;
    const float4 v = *(const float4*)(s + i);
    __half2* d = (__half2*)(dst + off + i);
    d[0] = __floats2half2_rn(v.x, v.y);
    d[1] = __floats2half2_rn(v.z, v.w);
}

__global__ void bcat_kernel(const float* __restrict__ a, const float* __restrict__ b) {
    const int i = blockIdx.x * 256 + threadIdx.x;
    g_bqk[i] = (i < CC) ? a[i] : b[i - CC];
}

// ---------------------------------------------------------------------------
// GroupNorm stats: per (b,g) mean/rstd -> per-channel scale/shift.
// Also zeroes g_sum (64 blocks x 512 threads cover all BB*NN entries).
// ---------------------------------------------------------------------------
__global__ void gn_stats(const float* __restrict__ x,
                         const float* __restrict__ gw,
                         const float* __restrict__ gb)
{
    const int b = blockIdx.x / GG;
    const int g = blockIdx.x % GG;
    const int cbase = g * CGG;
    const int tid = threadIdx.x;   // 512

    const int gi = blockIdx.x * 512 + tid;
    if (gi < BB * NN) g_sum[gi] = 0.f;

    const float* xg = x + ((size_t)b * CC + cbase) * NN;
    float s = 0.f, ss = 0.f;
    for (int idx = tid; idx < CGG * NN; idx += 512) {
        float v = xg[idx];
        s += v; ss += v * v;
    }
    #pragma unroll
    for (int o = 16; o > 0; o >>= 1) {
        s  += __shfl_xor_sync(0xffffffffu, s,  o);
        ss += __shfl_xor_sync(0xffffffffu, ss, o);
    }
    __shared__ float red[32];
    const int wid = tid >> 5, lane = tid & 31;
    if (lane == 0) { red[wid] = s; red[16 + wid] = ss; }
    __syncthreads();
    if (wid == 0) {
        s  = red[lane & 15];
        ss = red[16 + (lane & 15)];
        #pragma unroll
        for (int o = 8; o > 0; o >>= 1) {
            s  += __shfl_xor_sync(0xffffffffu, s,  o);
            ss += __shfl_xor_sync(0xffffffffu, ss, o);
        }
        if (lane < CGG) {
            const float inv_cnt = 1.f / (float)(CGG * NN);
            const float mean = s * inv_cnt;
            const float var  = ss * inv_cnt - mean * mean;
            const float rstd = rsqrtf(var + 1e-6f);
            const int c = cbase + lane;
            const float sc = rstd * gw[c];
            g_gnsc[b * CC + c] = sc;
            g_gnsh[b * CC + c] = gb[c] - mean * sc;
        }
    }
}

// GroupNorm apply + transpose -> g_hn fp16 [b*n, c], 32x32 tiles
__global__ void gn_apply(const float* __restrict__ x)
{
    __shared__ float t[32][33];
    const int n0 = blockIdx.x * 32;
    const int c0 = blockIdx.y * 32;
    const int b  = blockIdx.z;
    const int tx = threadIdx.x, ty = threadIdx.y;   // (32, 8)

    #pragma unroll
    for (int r = 0; r < 4; r++) {
        const int c = c0 + ty + 8 * r;
        t[ty + 8 * r][tx] = x[((size_t)b * CC + c) * NN + n0 + tx]
                            * g_gnsc[b * CC + c] + g_gnsh[b * CC + c];
    }
    __syncthreads();
    #pragma unroll
    for (int r = 0; r < 4; r++) {
        const int n = n0 + ty + 8 * r;
        g_hn[((size_t)b * NN + n) * CC + c0 + tx] = __float2half(t[tx][ty + 8 * r]);
    }
}

// ---------------------------------------------------------------------------
// fp16 mma NT GEMM with ldmatrix: C[m,n] = sum_k A[m,k]*B[n,k]  (fp32 acc)
// CTA 128x128, 256 threads, 8 warps (4Mx2N), warp tile 32x64.
// BK=64 halfs, 3-stage cp.async, row stride 72 halfs. 2 CTAs/SM -> 16 warps.
// EPI: 0 h16 | 1 +bias[col] h16 | 2 +bias[row] h16 | 3 +bias[row]+resid f32
//      4 exp h16 + per-column sums atomically added to g_sum
// ---------------------------------------------------------------------------
#define PADH 72
#define STAGES 3
#define SLOTH (128 * PADH)                         // 9216 halfs per stage per operand
#define GEMM_SMEM_BYTES (STAGES * 2 * SLOTH * 2)   // 110592

template <int EPI>
__global__ void __launch_bounds__(256, 2)
gemm_mma(const __half* __restrict__ A, int lda, size_t sA,
         const __half* __restrict__ B, int ldb, size_t sB,
         void*         __restrict__ Cv, int ldc, size_t sC,
         int K,
         const float* __restrict__ bias,
         const float* __restrict__ resid, size_t sR)
{
    extern __shared__ __half smem[];               // As[STAGES][SLOTH] | Bs[...]
    const uint32_t sb_a = smem_u32(smem);
    const uint32_t sb_b = sb_a + STAGES * SLOTH * 2;

    const int tid  = threadIdx.x;
    const int lane = tid & 31;
    const int wid  = tid >> 5;
    const int r    = lane >> 2;
    const int cq   = lane & 3;
    const int m_base = (wid & 3) * 32;     // 4 warps over M
    const int n_base = (wid >> 2) * 64;    // 2 warps over N

    // ldmatrix per-lane byte offsets (within one stage buffer)
    const int lrow = lane & 7;
    const int sel  = lane >> 3;        // 0..3 selects the 8x8 matrix
    uint32_t aoff[2], boff[4];
    #pragma unroll
    for (int i = 0; i < 2; i++)
        aoff[i] = (uint32_t)((m_base + i * 16 + (sel & 1) * 8 + lrow) * PADH
                             + (sel >> 1) * 8) * 2;
    #pragma unroll
    for (int j2 = 0; j2 < 4; j2++)
        boff[j2] = (uint32_t)((n_base + j2 * 16 + (sel >> 1) * 8 + lrow) * PADH
                              + (sel & 1) * 8) * 2;

    A += (size_t)blockIdx.z * sA;
    B += (size_t)blockIdx.z * sB;
    if (EPI == 3) resid += (size_t)blockIdx.z * sR;

    const int m0 = blockIdx.y * 128;
    const int n0 = blockIdx.x * 128;
    const __half* Ap = A + (size_t)m0 * lda;
    const __half* Bp = B + (size_t)n0 * ldb;

    const int nk = K >> 6;             // BK = 64 halfs

    auto issue = [&](int chunk) {
        const int st = chunk % STAGES;
        #pragma unroll
        for (int u = 0; u < 4; u++) {
            const int lin = u * 256 + tid;
            const int row = lin >> 3;
            const int c8  = (lin & 7) << 3;
            const uint32_t so = (uint32_t)(st * SLOTH + row * PADH + c8) * 2;
            cp_async16(sb_a + so, Ap + (size_t)row * lda + chunk * 64 + c8);
            cp_async16(sb_b + so, Bp + (size_t)row * ldb + chunk * 64 + c8);
        }
        asm volatile("cp.async.commit_group;" ::: "memory");
    };

    issue(0);
    issue(1);

    float acc[2][8][4];
    #pragma unroll
    for (int i = 0; i < 2; i++)
        #pragma unroll
        for (int j = 0; j < 8; j++)
            #pragma unroll
            for (int t = 0; t < 4; t++) acc[i][j][t] = 0.f;

    for (int c = 0; c < nk; c++) {
        asm volatile("cp.async.wait_group 1;" ::: "memory");
        __syncthreads();
        if (c + 2 < nk) issue(c + 2);

        const uint32_t abuf = sb_a + (uint32_t)(c % STAGES) * SLOTH * 2;
        const uint32_t bbuf = sb_b + (uint32_t)(c % STAGES) * SLOTH * 2;
        #pragma unroll
        for (int kb = 0; kb < 64; kb += 16) {
            uint32_t a[2][4], bb[4][4];
            #pragma unroll
            for (int i = 0; i < 2; i++)  ldsm_x4(a[i],  abuf + kb * 2 + aoff[i]);
            #pragma unroll
            for (int j2 = 0; j2 < 4; j2++) ldsm_x4(bb[j2], bbuf + kb * 2 + boff[j2]);
            #pragma unroll
            for (int i = 0; i < 2; i++)
                #pragma unroll
                for (int j = 0; j < 8; j++)
                    mma_f16(acc[i][j], a[i], bb[j >> 1][(j & 1) * 2],
                                             bb[j >> 1][(j & 1) * 2 + 1]);
        }
    }

    // Epilogue
    float*  Cf = (float*) Cv;
    __half* Ch = (__half*)Cv;
    if (EPI == 3) Cf += (size_t)blockIdx.z * sC;
    else          Ch += (size_t)blockIdx.z * sC;

    float csum[16];
    if (EPI == 4) {
        #pragma unroll
        for (int t = 0; t < 16; t++) csum[t] = 0.f;
    }

    #pragma unroll
    for (int i = 0; i < 2; i++) {
        const int row = m0 + m_base + i * 16 + r;
        float brow0 = 0.f, brow1 = 0.f;
        if (EPI == 2 || EPI == 3) { brow0 = bias[row]; brow1 = bias[row + 8]; }
        #pragma unroll
        for (int j = 0; j < 8; j++) {
            const int col = n0 + n_base + j * 8 + cq * 2;
            float v0 = acc[i][j][0], v1 = acc[i][j][1];
            float v2 = acc[i][j][2], v3 = acc[i][j][3];
            if (EPI == 1) {
                const float bc0 = bias[col], bc1 = bias[col + 1];
                v0 += bc0; v1 += bc1; v2 += bc0; v3 += bc1;
            }
            if (EPI == 2 || EPI == 3) { v0 += brow0; v1 += brow0; v2 += brow1; v3 += brow1; }
            if (EPI == 4) {
                v0 = fast_exp_scaled(v0); v1 = fast_exp_scaled(v1);
                v2 = fast_exp_scaled(v2); v3 = fast_exp_scaled(v3);
                csum[j * 2]     += v0 + v2;
                csum[j * 2 + 1] += v1 + v3;
            }
            if (EPI == 3) {
                const float2 r0 = *(const float2*)(resid + (size_t)row * ldc + col);
                const float2 r1 = *(const float2*)(resid + (size_t)(row + 8) * ldc + col);
                v0 += r0.x; v1 += r0.y; v2 += r1.x; v3 += r1.y;
                *(float2*)(Cf + (size_t)row * ldc + col)       = make_float2(v0, v1);
                *(float2*)(Cf + (size_t)(row + 8) * ldc + col) = make_float2(v2, v3);
            } else {
                *(__half2*)(Ch + (size_t)row * ldc + col)       = __floats2half2_rn(v0, v1);
                *(__half2*)(Ch + (size_t)(row + 8) * ldc + col) = __floats2half2_rn(v2, v3);
            }
        }
    }

    if (EPI == 4) {
        // Reduce over the 8 r-groups within the warp (lanes differing in bits 2..4)
        #pragma unroll
        for (int t = 0; t < 16; t++) {
            csum[t] += __shfl_xor_sync(0xffffffffu, csum[t], 4);
            csum[t] += __shfl_xor_sync(0xffffffffu, csum[t], 8);
            csum[t] += __shfl_xor_sync(0xffffffffu, csum[t], 16);
        }
        float* colacc = (float*)smem;       // overlay stage buffers (mainloop done)
        __syncthreads();
        if (tid < 128) colacc[tid] = 0.f;
        __syncthreads();
        if (lane < 4) {                      // lanes 0..3: cq = lane, r = 0
            #pragma unroll
            for (int j = 0; j < 8; j++) {
                atomicAdd(&colacc[n_base + j * 8 + cq * 2],     csum[j * 2]);
                atomicAdd(&colacc[n_base + j * 8 + cq * 2 + 1], csum[j * 2 + 1]);
            }
        }
        __syncthreads();
        if (tid < 128)
            atomicAdd(&g_sum[(size_t)blockIdx.z * NN + n0 + tid], colacc[tid]);
    }
}

// ---------------------------------------------------------------------------
// vt[c, g] /= s[g]   (softmax denominator folded into V; rcp inline)
// ---------------------------------------------------------------------------
__global__ void vtscale_kernel() {
    const size_t idx = (size_t)blockIdx.x * 256 + threadIdx.x;  // half2 index
    __half2 v = ((__half2*)g_vt)[idx];
    const int g2 = (int)(idx & (BB * NN / 2 - 1));
    const float2 sv = ((const float2*)g_sum)[g2];
    const float2 vf = __half22float2(v);
    ((__half2*)g_vt)[idx] = __floats2half2_rn(__fdividef(vf.x, sv.x),
                                              __fdividef(vf.y, sv.y));
}

// ---------------------------------------------------------------------------
extern "C" void kernel_launch(void* const* d_in, const int* in_sizes, int n_in,
                              void* d_out, int out_size)
{
    const float* x  = (const float*)d_in[0];
    const float* nw = (const float*)d_in[1];
    const float* nb = (const float*)d_in[2];
    const float* wq = (const float*)d_in[3];
    const float* bq = (const float*)d_in[4];
    const float* wk = (const float*)d_in[5];
    const float* bk = (const float*)d_in[6];
    const float* wv = (const float*)d_in[7];
    const float* bv = (const float*)d_in[8];
    const float* wp = (const float*)d_in[9];
    const float* bp = (const float*)d_in[10];
    float* out = (float*)d_out;

    __half *hn, *qk, *vt, *attnT, *h2, *w16;
    float *bqk;
    cudaGetSymbolAddress((void**)&hn,    g_hn);
    cudaGetSymbolAddress((void**)&qk,    g_qk);
    cudaGetSymbolAddress((void**)&vt,    g_vt);
    cudaGetSymbolAddress((void**)&attnT, g_attnT);
    cudaGetSymbolAddress((void**)&h2,    g_h2);
    cudaGetSymbolAddress((void**)&w16,   g_w16);
    cudaGetSymbolAddress((void**)&bqk,   g_bqk);
    __half* wqk16 = w16;                              // [wq ; wk] rows 0..1023
    __half* wv16 = w16 + (size_t)2 * CC * CC;
    __half* wp16 = w16 + (size_t)3 * CC * CC;
    __half* qp = qk;                                  // q cols 0-511
    __half* kp = qk + CC;                             // k cols 512-1023

    cudaFuncSetAttribute(gemm_mma<0>, cudaFuncAttributeMaxDynamicSharedMemorySize, GEMM_SMEM_BYTES);
    cudaFuncSetAttribute(gemm_mma<1>, cudaFuncAttributeMaxDynamicSharedMemorySize, GEMM_SMEM_BYTES);
    cudaFuncSetAttribute(gemm_mma<2>, cudaFuncAttributeMaxDynamicSharedMemorySize, GEMM_SMEM_BYTES);
    cudaFuncSetAttribute(gemm_mma<3>, cudaFuncAttributeMaxDynamicSharedMemorySize, GEMM_SMEM_BYTES);
    cudaFuncSetAttribute(gemm_mma<4>, cudaFuncAttributeMaxDynamicSharedMemorySize, GEMM_SMEM_BYTES);

    const size_t sNC   = (size_t)NN * CC;
    const size_t sNQK  = (size_t)NN * 2 * CC;
    const size_t sNN2  = (size_t)NN * NN;
    const size_t sCN   = (size_t)CC * NN;

    // 0) Weights -> fp16; bias concat
    f2h4_kernel<<<dim3((CC * CC) / 1024, 4), 256>>>(wq, wk, wv, wp, w16);
    bcat_kernel<<<(2 * CC) / 256, 256>>>(bq, bk);

    // 1) GroupNorm -> hn fp16 (also zeroes g_sum)
    gn_stats<<<BB * GG, 512>>>(x, nw, nb);
    gn_apply<<<dim3(NN / 32, CC / 32, BB), dim3(32, 8)>>>(x);

    // 2) fused qk[i, 0:1024] = hn[i,:]·[wq;wk][c,:] + [bq;bk]   M=8192 N=1024 K=512
    gemm_mma<1><<<dim3(8, 64, 1), 256, GEMM_SMEM_BYTES>>>(hn, CC, 0, wqk16, CC, 0,
                                                          qk, 2 * CC, 0, CC, bqk, nullptr, 0);
    //    vt[c, b*N+i] = wv[c,:]·hn[i,:] + bv[c]   M=512 N=8192 K=512
    gemm_mma<2><<<dim3(64, 4, 1), 256, GEMM_SMEM_BYTES>>>(wv16, CC, 0, hn, CC, 0,
                                                          vt, BB * NN, 0, CC, bv, nullptr, 0);

    // 3) attnT[j,i] = exp(scale*(k_j·q_i)) * 2^-12; column sums -> g_sum
    gemm_mma<4><<<dim3(32, 32, 2), 256, GEMM_SMEM_BYTES>>>(kp, 2 * CC, sNQK, qp, 2 * CC, sNQK,
                                                           attnT, NN, sNN2, CC,
                                                           nullptr, nullptr, 0);

    // 4) 1/s folded into vt
    vtscale_kernel<<<(int)((size_t)CC * BB * NN / 2 / 256), 256>>>();

    // 5) h2[j,c] = sum_i attnT[j,i] * vt'[c, b*N+i]   M=4096 N=512 K=4096
    gemm_mma<0><<<dim3(4, 32, 2), 256, GEMM_SMEM_BYTES>>>(attnT, NN, sNN2,
                                                          vt, BB * NN, (size_t)NN,
                                                          h2, CC, sNC, NN,
                                                          nullptr, nullptr, 0);

    // 6) out[o,j] = x + bp[o] + sum_c wp[o,c]*h2[j,c]   M=512 N=4096 K=512
    gemm_mma<3><<<dim3(32, 4, 2), 256, GEMM_SMEM_BYTES>>>(wp16, CC, 0, h2, CC, sNC,
                                                          out, NN, sCN, CC,
                                                          bp, x, sCN);
}

// round 16
// speedup vs baseline: 1.0776x; 1.0776x over previous
#include <cuda_runtime.h>
#include <cuda_fp16.h>
#include <cstdint>

#define BB 2
#define CC 512
#define NN 4096
#define GG 32
#define CGG 16
#define SM_SCALE 0.044194173824159216f

// ---------------- scratch (__device__ globals; allocation-free rule) --------
__device__ __half g_hn   [(size_t)BB * NN * CC];       // groupnorm out [b*n, c]
__device__ __half g_qk   [(size_t)BB * NN * 2 * CC];   // [b*n, 1024]: q 0-511, k 512-1023
__device__ __half g_vt   [(size_t)CC * BB * NN];       // [c, b*n]
__device__ __half g_attnT[(size_t)BB * NN * NN];       // exp(logits)*2^-12, [b, j, i]
__device__ __half g_h2   [(size_t)BB * NN * CC];       // [b, j, c]
__device__ __half g_w16  [4][(size_t)CC * CC];         // wq, wk, wv, wp fp16 (wq|wk contiguous)
__device__ float  g_sum  [BB * NN];                    // colsum of exp
__device__ float  g_bqk  [2 * CC];                     // [bq ; bk]
__device__ float  g_gnsc [BB * CC];                    // per-channel scale
__device__ float  g_gnsh [BB * CC];                    // per-channel shift

// ---------------- second stream + events (host objects; created at load) ----
struct StreamPack {
    cudaStream_t s2;
    cudaEvent_t eFork, eW, eGN, eVT;
    StreamPack() {
        cudaStreamCreateWithFlags(&s2, cudaStreamNonBlocking);
        cudaEventCreateWithFlags(&eFork, cudaEventDisableTiming);
        cudaEventCreateWithFlags(&eW,    cudaEventDisableTiming);
        cudaEventCreateWithFlags(&eGN,   cudaEventDisableTiming);
        cudaEventCreateWithFlags(&eVT,   cudaEventDisableTiming);
    }
};
static StreamPack g_sp;

// ---------------------------------------------------------------------------
__device__ __forceinline__ uint32_t smem_u32(const void* p) {
    uint32_t a;
    asm("{ .reg .u64 t; cvta.to.shared.u64 t, %1; cvt.u32.u64 %0, t; }"
        : "=r"(a) : "l"(p));
    return a;
}
__device__ __forceinline__ void cp_async16(uint32_t saddr, const void* g) {
    asm volatile("cp.async.cg.shared.global [%0], [%1], 16;" :: "r"(saddr), "l"(g));
}
__device__ __forceinline__ void ldsm_x4(uint32_t d[4], uint32_t addr) {
    asm volatile("ldmatrix.sync.aligned.m8n8.x4.shared.b16 {%0,%1,%2,%3}, [%4];"
                 : "=r"(d[0]), "=r"(d[1]), "=r"(d[2]), "=r"(d[3]) : "r"(addr));
}
__device__ __forceinline__ void mma_f16(float d[4], const uint32_t a[4],
                                        uint32_t b0, uint32_t b1) {
    asm volatile(
        "mma.sync.aligned.m16n8k16.row.col.f32.f16.f16.f32 "
        "{%0,%1,%2,%3}, {%4,%5,%6,%7}, {%8,%9}, {%0,%1,%2,%3};"
        : "+f"(d[0]), "+f"(d[1]), "+f"(d[2]), "+f"(d[3])
        : "r"(a[0]), "r"(a[1]), "r"(a[2]), "r"(a[3]), "r"(b0), "r"(b1));
}

// exp(SM_SCALE*v) * 2^-12 on the FMA pipe (no MUFU).
__device__ __forceinline__ float fast_exp_scaled(float v) {
    float t = v * (SM_SCALE * 1.4426950408889634f);
    float z = t + 12582912.f;                 // 1.5*2^23: round-to-nearest
    int   i = __float_as_int(z) - 0x4B400000;
    float f = t - (z - 12582912.f);           // frac in [-0.5, 0.5]
    float p =            1.3333649e-3f;
    p = fmaf(p, f, 9.6179357e-3f);
    p = fmaf(p, f, 5.5504109e-2f);
    p = fmaf(p, f, 2.4022604e-1f);
    p = fmaf(p, f, 6.9314718e-1f);
    p = fmaf(p, f, 1.0f);
    return p * __int_as_float((i + 127 - 12) << 23);   // fold 2^-12
}

// ---------------------------------------------------------------------------
// Weights fp32 -> fp16 (all four in one launch; y selects the matrix)
// ---------------------------------------------------------------------------
__global__ void f2h4_kernel(const float* __restrict__ s0, const float* __restrict__ s1,
                            const float* __restrict__ s2, const float* __restrict__ s3,
                            __half* __restrict__ dst) {
    const float* s = (blockIdx.y == 0) ? s0 : (blockIdx.y == 1) ? s1
                   : (blockIdx.y == 2) ? s2 : s3;
    const size_t off = (size_t)blockIdx.y * CC * CC;
    const int i = (blockIdx.x * 256 + threadIdx.x) * 4;
    const float4 v = *(const float4*)(s + i);
    __half2* d = (__half2*)(dst + off + i);
    d[0] = __floats2half2_rn(v.x, v.y);
    d[1] = __floats2half2_rn(v.z, v.w);
}

__global__ void bcat_kernel(const float* __restrict__ a, const float* __restrict__ b) {
    const int i = blockIdx.x * 256 + threadIdx.x;
    g_bqk[i] = (i < CC) ? a[i] : b[i - CC];
}

// ---------------------------------------------------------------------------
// GroupNorm stats: per (b,g) mean/rstd -> per-channel scale/shift.
// Also zeroes g_sum (64 blocks x 512 threads cover all BB*NN entries).
// ---------------------------------------------------------------------------
__global__ void gn_stats(const float* __restrict__ x,
                         const float* __restrict__ gw,
                         const float* __restrict__ gb)
{
    const int b = blockIdx.x / GG;
    const int g = blockIdx.x % GG;
    const int cbase = g * CGG;
    const int tid = threadIdx.x;   // 512

    const int gi = blockIdx.x * 512 + tid;
    if (gi < BB * NN) g_sum[gi] = 0.f;

    const float* xg = x + ((size_t)b * CC + cbase) * NN;
    float s = 0.f, ss = 0.f;
    for (int idx = tid; idx < CGG * NN; idx += 512) {
        float v = xg[idx];
        s += v; ss += v * v;
    }
    #pragma unroll
    for (int o = 16; o > 0; o >>= 1) {
        s  += __shfl_xor_sync(0xffffffffu, s,  o);
        ss += __shfl_xor_sync(0xffffffffu, ss, o);
    }
    __shared__ float red[32];
    const int wid = tid >> 5, lane = tid & 31;
    if (lane == 0) { red[wid] = s; red[16 + wid] = ss; }
    __syncthreads();
    if (wid == 0) {
        s  = red[lane & 15];
        ss = red[16 + (lane & 15)];
        #pragma unroll
        for (int o = 8; o > 0; o >>= 1) {
            s  += __shfl_xor_sync(0xffffffffu, s,  o);
            ss += __shfl_xor_sync(0xffffffffu, ss, o);
        }
        if (lane < CGG) {
            const float inv_cnt = 1.f / (float)(CGG * NN);
            const float mean = s * inv_cnt;
            const float var  = ss * inv_cnt - mean * mean;
            const float rstd = rsqrtf(var + 1e-6f);
            const int c = cbase + lane;
            const float sc = rstd * gw[c];
            g_gnsc[b * CC + c] = sc;
            g_gnsh[b * CC + c] = gb[c] - mean * sc;
        }
    }
}

// GroupNorm apply + transpose -> g_hn fp16 [b*n, c], 32x32 tiles
__global__ void gn_apply(const float* __restrict__ x)
{
    __shared__ float t[32][33];
    const int n0 = blockIdx.x * 32;
    const int c0 = blockIdx.y * 32;
    const int b  = blockIdx.z;
    const int tx = threadIdx.x, ty = threadIdx.y;   // (32, 8)

    #pragma unroll
    for (int r = 0; r < 4; r++) {
        const int c = c0 + ty + 8 * r;
        t[ty + 8 * r][tx] = x[((size_t)b * CC + c) * NN + n0 + tx]
                            * g_gnsc[b * CC + c] + g_gnsh[b * CC + c];
    }
    __syncthreads();
    #pragma unroll
    for (int r = 0; r < 4; r++) {
        const int n = n0 + ty + 8 * r;
        g_hn[((size_t)b * NN + n) * CC + c0 + tx] = __float2half(t[tx][ty + 8 * r]);
    }
}

// ---------------------------------------------------------------------------
// fp16 mma NT GEMM with ldmatrix: C[m,n] = sum_k A[m,k]*B[n,k]  (fp32 acc)
// CTA 128x128, 128 threads, 4 warps (2Mx2N), warp tile 64x64.
// BK=64 halfs, 3-stage cp.async, row stride 72 halfs. (R12 config.)
// EPI: 0 h16 | 1 +bias[col] h16 | 2 +bias[row] h16 | 3 +bias[row]+resid f32
//      4 exp h16 + per-column sums atomically added to g_sum
// ---------------------------------------------------------------------------
#define PADH 72
#define STAGES 3
#define SLOTH (128 * PADH)                         // 9216 halfs per stage per operand
#define GEMM_SMEM_BYTES (STAGES * 2 * SLOTH * 2)   // 110592

template <int EPI>
__global__ void __launch_bounds__(128, 2)
gemm_mma(const __half* __restrict__ A, int lda, size_t sA,
         const __half* __restrict__ B, int ldb, size_t sB,
         void*         __restrict__ Cv, int ldc, size_t sC,
         int K,
         const float* __restrict__ bias,
         const float* __restrict__ resid, size_t sR)
{
    extern __shared__ __half smem[];               // As[STAGES][SLOTH] | Bs[...]
    const uint32_t sb_a = smem_u32(smem);
    const uint32_t sb_b = sb_a + STAGES * SLOTH * 2;

    const int tid  = threadIdx.x;
    const int lane = tid & 31;
    const int wid  = tid >> 5;
    const int r    = lane >> 2;
    const int cq   = lane & 3;
    const int m_base = (wid & 1) * 64;
    const int n_base = (wid >> 1) * 64;

    // ldmatrix per-lane byte offsets (within one stage buffer)
    const int lrow = lane & 7;
    const int sel  = lane >> 3;        // 0..3 selects the 8x8 matrix
    uint32_t aoff[4], boff[4];
    #pragma unroll
    for (int i = 0; i < 4; i++)
        aoff[i] = (uint32_t)((m_base + i * 16 + (sel & 1) * 8 + lrow) * PADH
                             + (sel >> 1) * 8) * 2;
    #pragma unroll
    for (int j2 = 0; j2 < 4; j2++)
        boff[j2] = (uint32_t)((n_base + j2 * 16 + (sel >> 1) * 8 + lrow) * PADH
                              + (sel & 1) * 8) * 2;

    A += (size_t)blockIdx.z * sA;
    B += (size_t)blockIdx.z * sB;
    if (EPI == 3) resid += (size_t)blockIdx.z * sR;

    const int m0 = blockIdx.y * 128;
    const int n0 = blockIdx.x * 128;
    const __half* Ap = A + (size_t)m0 * lda;
    const __half* Bp = B + (size_t)n0 * ldb;

    const int nk = K >> 6;             // BK = 64 halfs

    auto issue = [&](int chunk) {
        const int st = chunk % STAGES;
        #pragma unroll
        for (int u = 0; u < 8; u++) {
            const int lin = u * 128 + tid;
            const int row = lin >> 3;
            const int c8  = (lin & 7) << 3;
            const uint32_t so = (uint32_t)(st * SLOTH + row * PADH + c8) * 2;
            cp_async16(sb_a + so, Ap + (size_t)row * lda + chunk * 64 + c8);
            cp_async16(sb_b + so, Bp + (size_t)row * ldb + chunk * 64 + c8);
        }
        asm volatile("cp.async.commit_group;" ::: "memory");
    };

    issue(0);
    issue(1);

    float acc[4][8][4];
    #pragma unroll
    for (int i = 0; i < 4; i++)
        #pragma unroll
        for (int j = 0; j < 8; j++)
            #pragma unroll
            for (int t = 0; t < 4; t++) acc[i][j][t] = 0.f;

    for (int c = 0; c < nk; c++) {
        asm volatile("cp.async.wait_group 1;" ::: "memory");
        __syncthreads();
        if (c + 2 < nk) issue(c + 2);

        const uint32_t abuf = sb_a + (uint32_t)(c % STAGES) * SLOTH * 2;
        const uint32_t bbuf = sb_b + (uint32_t)(c % STAGES) * SLOTH * 2;
        #pragma unroll
        for (int kb = 0; kb < 64; kb += 16) {
            uint32_t a[4][4], bb[4][4];
            #pragma unroll
            for (int i = 0; i < 4; i++)  ldsm_x4(a[i],  abuf + kb * 2 + aoff[i]);
            #pragma unroll
            for (int j2 = 0; j2 < 4; j2++) ldsm_x4(bb[j2], bbuf + kb * 2 + boff[j2]);
            #pragma unroll
            for (int i = 0; i < 4; i++)
                #pragma unroll
                for (int j = 0; j < 8; j++)
                    mma_f16(acc[i][j], a[i], bb[j >> 1][(j & 1) * 2],
                                             bb[j >> 1][(j & 1) * 2 + 1]);
        }
    }

    // Epilogue
    float*  Cf = (float*) Cv;
    __half* Ch = (__half*)Cv;
    if (EPI == 3) Cf += (size_t)blockIdx.z * sC;
    else          Ch += (size_t)blockIdx.z * sC;

    float csum[16];
    if (EPI == 4) {
        #pragma unroll
        for (int t = 0; t < 16; t++) csum[t] = 0.f;
    }

    #pragma unroll
    for (int i = 0; i < 4; i++) {
        const int row = m0 + m_base + i * 16 + r;
        float brow0 = 0.f, brow1 = 0.f;
        if (EPI == 2 || EPI == 3) { brow0 = bias[row]; brow1 = bias[row + 8]; }
        #pragma unroll
        for (int j = 0; j < 8; j++) {
            const int col = n0 + n_base + j * 8 + cq * 2;
            float v0 = acc[i][j][0], v1 = acc[i][j][1];
            float v2 = acc[i][j][2], v3 = acc[i][j][3];
            if (EPI == 1) {
                const float bc0 = bias[col], bc1 = bias[col + 1];
                v0 += bc0; v1 += bc1; v2 += bc0; v3 += bc1;
            }
            if (EPI == 2 || EPI == 3) { v0 += brow0; v1 += brow0; v2 += brow1; v3 += brow1; }
            if (EPI == 4) {
                v0 = fast_exp_scaled(v0); v1 = fast_exp_scaled(v1);
                v2 = fast_exp_scaled(v2); v3 = fast_exp_scaled(v3);
                csum[j * 2]     += v0 + v2;
                csum[j * 2 + 1] += v1 + v3;
            }
            if (EPI == 3) {
                const float2 r0 = *(const float2*)(resid + (size_t)row * ldc + col);
                const float2 r1 = *(const float2*)(resid + (size_t)(row + 8) * ldc + col);
                v0 += r0.x; v1 += r0.y; v2 += r1.x; v3 += r1.y;
                *(float2*)(Cf + (size_t)row * ldc + col)       = make_float2(v0, v1);
                *(float2*)(Cf + (size_t)(row + 8) * ldc + col) = make_float2(v2, v3);
            } else {
                *(__half2*)(Ch + (size_t)row * ldc + col)       = __floats2half2_rn(v0, v1);
                *(__half2*)(Ch + (size_t)(row + 8) * ldc + col) = __floats2half2_rn(v2, v3);
            }
        }
    }

    if (EPI == 4) {
        // Reduce over the 8 r-groups within the warp (lanes differing in bits 2..4)
        #pragma unroll
        for (int t = 0; t < 16; t++) {
            csum[t] += __shfl_xor_sync(0xffffffffu, csum[t], 4);
            csum[t] += __shfl_xor_sync(0xffffffffu, csum[t], 8);
            csum[t] += __shfl_xor_sync(0xffffffffu, csum[t], 16);
        }
        float* colacc = (float*)smem;       // overlay stage buffers (mainloop done)
        __syncthreads();
        if (tid < 128) colacc[tid] = 0.f;
        __syncthreads();
        if (lane < 4) {                      // lanes 0..3: cq = lane, r = 0
            #pragma unroll
            for (int j = 0; j < 8; j++) {
                atomicAdd(&colacc[n_base + j * 8 + cq * 2],     csum[j * 2]);
                atomicAdd(&colacc[n_base + j * 8 + cq * 2 + 1], csum[j * 2 + 1]);
            }
        }
        __syncthreads();
        if (tid < 128)
            atomicAdd(&g_sum[(size_t)blockIdx.z * NN + n0 + tid], colacc[tid]);
    }
}

// ---------------------------------------------------------------------------
// vt[c, g] /= s[g]   (softmax denominator folded into V; rcp inline)
// ---------------------------------------------------------------------------
__global__ void vtscale_kernel() {
    const size_t idx = (size_t)blockIdx.x * 256 + threadIdx.x;  // half2 index
    __half2 v = ((__half2*)g_vt)[idx];
    const int g2 = (int)(idx & (BB * NN / 2 - 1));
    const float2 sv = ((const float2*)g_sum)[g2];
    const float2 vf = __half22float2(v);
    ((__half2*)g_vt)[idx] = __floats2half2_rn(__fdividef(vf.x, sv.x),
                                              __fdividef(vf.y, sv.y));
}

// ---------------------------------------------------------------------------
extern "C" void kernel_launch(void* const* d_in, const int* in_sizes, int n_in,
                              void* d_out, int out_size)
{
    const float* x  = (const float*)d_in[0];
    const float* nw = (const float*)d_in[1];
    const float* nb = (const float*)d_in[2];
    const float* wq = (const float*)d_in[3];
    const float* bq = (const float*)d_in[4];
    const float* wk = (const float*)d_in[5];
    const float* bk = (const float*)d_in[6];
    const float* wv = (const float*)d_in[7];
    const float* bv = (const float*)d_in[8];
    const float* wp = (const float*)d_in[9];
    const float* bp = (const float*)d_in[10];
    float* out = (float*)d_out;

    __half *hn, *qk, *vt, *attnT, *h2, *w16;
    float *bqk;
    cudaGetSymbolAddress((void**)&hn,    g_hn);
    cudaGetSymbolAddress((void**)&qk,    g_qk);
    cudaGetSymbolAddress((void**)&vt,    g_vt);
    cudaGetSymbolAddress((void**)&attnT, g_attnT);
    cudaGetSymbolAddress((void**)&h2,    g_h2);
    cudaGetSymbolAddress((void**)&w16,   g_w16);
    cudaGetSymbolAddress((void**)&bqk,   g_bqk);
    __half* wqk16 = w16;                              // [wq ; wk] rows 0..1023
    __half* wv16 = w16 + (size_t)2 * CC * CC;
    __half* wp16 = w16 + (size_t)3 * CC * CC;
    __half* qp = qk;                                  // q cols 0-511
    __half* kp = qk + CC;                             // k cols 512-1023

    cudaFuncSetAttribute(gemm_mma<0>, cudaFuncAttributeMaxDynamicSharedMemorySize, GEMM_SMEM_BYTES);
    cudaFuncSetAttribute(gemm_mma<1>, cudaFuncAttributeMaxDynamicSharedMemorySize, GEMM_SMEM_BYTES);
    cudaFuncSetAttribute(gemm_mma<2>, cudaFuncAttributeMaxDynamicSharedMemorySize, GEMM_SMEM_BYTES);
    cudaFuncSetAttribute(gemm_mma<3>, cudaFuncAttributeMaxDynamicSharedMemorySize, GEMM_SMEM_BYTES);
    cudaFuncSetAttribute(gemm_mma<4>, cudaFuncAttributeMaxDynamicSharedMemorySize, GEMM_SMEM_BYTES);

    const size_t sNC   = (size_t)NN * CC;
    const size_t sNQK  = (size_t)NN * 2 * CC;
    const size_t sNN2  = (size_t)NN * NN;
    const size_t sCN   = (size_t)CC * NN;

    cudaStream_t s2 = g_sp.s2;

    // fork: s2 joins the (captured) main stream's timeline
    cudaEventRecord(g_sp.eFork, 0);
    cudaStreamWaitEvent(s2, g_sp.eFork, 0);

    // ---- stream s2: weight conversion (independent of groupnorm) ----
    f2h4_kernel<<<dim3((CC * CC) / 1024, 4), 256, 0, s2>>>(wq, wk, wv, wp, w16);
    bcat_kernel<<<(2 * CC) / 256, 256, 0, s2>>>(bq, bk);
    cudaEventRecord(g_sp.eW, s2);

    // ---- stream 0: GroupNorm (also zeroes g_sum) ----
    gn_stats<<<BB * GG, 512>>>(x, nw, nb);
    gn_apply<<<dim3(NN / 32, CC / 32, BB), dim3(32, 8)>>>(x);
    cudaEventRecord(g_sp.eGN, 0);

    // ---- stream s2: VT gemm (needs hn + wv16), overlaps QK+logits on s0 ----
    cudaStreamWaitEvent(s2, g_sp.eGN, 0);
    gemm_mma<2><<<dim3(64, 4, 1), 128, GEMM_SMEM_BYTES, s2>>>(
        wv16, CC, 0, hn, CC, 0, vt, BB * NN, 0, CC, bv, nullptr, 0);
    cudaEventRecord(g_sp.eVT, s2);

    // ---- stream 0: QK fused gemm (needs wqk16/bqk from s2) ----
    cudaStreamWaitEvent(0, g_sp.eW, 0);
    gemm_mma<1><<<dim3(8, 64, 1), 128, GEMM_SMEM_BYTES>>>(
        hn, CC, 0, wqk16, CC, 0, qk, 2 * CC, 0, CC, bqk, nullptr, 0);

    // logits: attnT[j,i] = exp(scale*(k_j·q_i)) * 2^-12; colsums -> g_sum
    gemm_mma<4><<<dim3(32, 32, 2), 128, GEMM_SMEM_BYTES>>>(
        kp, 2 * CC, sNQK, qp, 2 * CC, sNQK, attnT, NN, sNN2, CC,
        nullptr, nullptr, 0);

    // join: vtscale needs vt (s2) and g_sum (s0)
    cudaStreamWaitEvent(0, g_sp.eVT, 0);
    vtscale_kernel<<<(int)((size_t)CC * BB * NN / 2 / 256), 256>>>();

    // AV: h2[j,c] = sum_i attnT[j,i] * vt'[c, b*N+i]
    gemm_mma<0><<<dim3(4, 32, 2), 128, GEMM_SMEM_BYTES>>>(
        attnT, NN, sNN2, vt, BB * NN, (size_t)NN, h2, CC, sNC, NN,
        nullptr, nullptr, 0);

    // proj: out[o,j] = x + bp[o] + sum_c wp[o,c]*h2[j,c]
    gemm_mma<3><<<dim3(32, 4, 2), 128, GEMM_SMEM_BYTES>>>(
        wp16, CC, 0, h2, CC, sNC, out, NN, sCN, CC, bp, x, sCN);
}